// round 12
// baseline (speedup 1.0000x reference)
#include <cuda_runtime.h>
#include <cuda_bf16.h>
#include <cstdint>

#define BB 4
#define SS 1024
#define DD 2048
#define RPB 8                   // rows per block
#define NBLK (DD / RPB)         // 256 blocks

// Scratch (allocation-free rule: __device__ globals; device-side refs only)
__device__ float g_v[BB * DD];
__device__ float g_o[BB * DD];

// Dynamic smem layout (bytes)
#define SM_MBAR0 0
#define SM_MBAR1 8
#define SM_BV    128                    // 8 KB   (stage 1 only)
#define SM_X     (SM_BV + 8192)        // 32 KB
#define SM_W     (SM_X + 32768)        // 64 KB
#define SM_TOTAL (SM_W + 65536)        // 106,624 B

__device__ __forceinline__ uint32_t smem_u32(const void* p) {
    return (uint32_t)__cvta_generic_to_shared(p);
}
__device__ __forceinline__ void mbar_init(uint32_t mbar, uint32_t cnt) {
    asm volatile("mbarrier.init.shared.b64 [%0], %1;" :: "r"(mbar), "r"(cnt) : "memory");
}
__device__ __forceinline__ void mbar_expect(uint32_t mbar, uint32_t bytes) {
    asm volatile("mbarrier.arrive.expect_tx.shared.b64 _, [%0], %1;"
                 :: "r"(mbar), "r"(bytes) : "memory");
}
__device__ __forceinline__ void mbar_wait(uint32_t mbar, uint32_t parity) {
    asm volatile(
        "{\n\t.reg .pred P;\n\t"
        "W_%=:\n\t"
        "mbarrier.try_wait.parity.acquire.cta.shared::cta.b64 P, [%0], %1;\n\t"
        "@!P bra W_%=;\n\t}"
        :: "r"(mbar), "r"(parity) : "memory");
}
// Bulk async copy global -> shared, completion via mbarrier tx-bytes.
__device__ __forceinline__ void bulk_g2s(uint32_t dst, const void* src,
                                         uint32_t bytes, uint32_t mbar) {
    asm volatile(
        "cp.async.bulk.shared::cluster.global.mbarrier::complete_tx::bytes "
        "[%0], [%1], %2, [%3];"
        :: "r"(dst), "l"(src), "r"(bytes), "r"(mbar) : "memory");
}

// y[b][gr] = sum_k x[b][k] * W[gr][k]  for 8 rows per block, full K.
// STAGE 0: x = cond (global input), y = g_v (bias folded later).
// STAGE 1: x = g_v + bv,            y = g_o (bo folded in bcast).
// W slab (64 KB) + x (32 KB) (+bv 8 KB) arrive via TMA bulk copies.
template<int STAGE>
__global__ __launch_bounds__(256) void gemv_tma(const float* __restrict__ W,
                                                const float* __restrict__ cond,
                                                const float* __restrict__ bv) {
    extern __shared__ char smem[];
    const uint32_t base = smem_u32(smem);
    const uint32_t mb0 = base + SM_MBAR0;
    const uint32_t mb1 = base + SM_MBAR1;
    const int tid  = threadIdx.x;
    const int wid  = tid >> 5;
    const int lane = tid & 31;
    const int r0   = blockIdx.x * RPB;

    if (tid == 0) { mbar_init(mb0, 1); mbar_init(mb1, 1); }
    __syncthreads();

    if (tid == 0) {
        asm volatile("fence.proxy.async.shared::cta;" ::: "memory");
        const float* xsrc = (STAGE == 0) ? cond : g_v;
        uint32_t exp0 = 32768 + 32768 + (STAGE == 1 ? 8192 : 0);
        mbar_expect(mb0, exp0);
        bulk_g2s(base + SM_X, xsrc, 32768, mb0);                    // x: 4x2048 f32
        bulk_g2s(base + SM_W, W + (size_t)r0 * DD, 32768, mb0);     // rows 0-3
        if (STAGE == 1) bulk_g2s(base + SM_BV, bv, 8192, mb0);      // bv
        mbar_expect(mb1, 32768);
        bulk_g2s(base + SM_W + 32768, W + (size_t)(r0 + 4) * DD, 32768, mb1); // rows 4-7
    }

    // Warp w owns row r0+w. Rows 0-3 need only mb0; rows 4-7 also mb1.
    mbar_wait(mb0, 0);
    if (wid >= 4) mbar_wait(mb1, 0);

    const float4* Wrow = (const float4*)(smem + SM_W) + wid * (DD / 4);
    const float4* xs   = (const float4*)(smem + SM_X);
    const float4* bvS  = (const float4*)(smem + SM_BV);

    float a0 = 0.f, a1 = 0.f, a2 = 0.f, a3 = 0.f;
    #pragma unroll
    for (int i = 0; i < DD / 4 / 32; ++i) {      // 16 iters
        const int k4 = i * 32 + lane;
        const float4 wv = Wrow[k4];
        float4 x0 = xs[0 * (DD / 4) + k4];
        float4 x1 = xs[1 * (DD / 4) + k4];
        float4 x2 = xs[2 * (DD / 4) + k4];
        float4 x3 = xs[3 * (DD / 4) + k4];
        if (STAGE == 1) {
            const float4 bb = bvS[k4];
            x0.x += bb.x; x0.y += bb.y; x0.z += bb.z; x0.w += bb.w;
            x1.x += bb.x; x1.y += bb.y; x1.z += bb.z; x1.w += bb.w;
            x2.x += bb.x; x2.y += bb.y; x2.z += bb.z; x2.w += bb.w;
            x3.x += bb.x; x3.y += bb.y; x3.z += bb.z; x3.w += bb.w;
        }
        a0 += wv.x * x0.x + wv.y * x0.y + wv.z * x0.z + wv.w * x0.w;
        a1 += wv.x * x1.x + wv.y * x1.y + wv.z * x1.z + wv.w * x1.w;
        a2 += wv.x * x2.x + wv.y * x2.y + wv.z * x2.z + wv.w * x2.w;
        a3 += wv.x * x3.x + wv.y * x3.y + wv.z * x3.z + wv.w * x3.w;
    }
    #pragma unroll
    for (int off = 16; off > 0; off >>= 1) {
        a0 += __shfl_xor_sync(0xffffffffu, a0, off);
        a1 += __shfl_xor_sync(0xffffffffu, a1, off);
        a2 += __shfl_xor_sync(0xffffffffu, a2, off);
        a3 += __shfl_xor_sync(0xffffffffu, a3, off);
    }
    if (lane == 0) {
        float* y = (STAGE == 0) ? g_v : g_o;
        const int gr = r0 + wid;
        y[0 * DD + gr] = a0;
        y[1 * DD + gr] = a1;
        y[2 * DD + gr] = a2;
        y[3 * DD + gr] = a3;
    }
}

__device__ __forceinline__ float4 f4add(float4 a, float4 b) {
    return make_float4(a.x + b.x, a.y + b.y, a.z + b.z, a.w + b.w);
}

// out[b][s][:] = g_o[b][:] + bo, broadcast over s; 8 stores per owner thread.
__global__ __launch_bounds__(256) void bcast_kernel(float4* __restrict__ out,
                                                    const float* __restrict__ bo) {
    const int t  = blockIdx.x * 256 + threadIdx.x;   // 256K threads
    const int d4 = t & 511;
    const int g  = t >> 9;
    const int b  = g >> 7;           // 0..3
    const int s8 = (g & 127) * 8;

    const float4* o4  = (const float4*)g_o;
    const float4* bo4 = (const float4*)bo;
    const float4 o = f4add(o4[b * 512 + d4], bo4[d4]);

    float4* dst = out + ((size_t)(b * SS + s8) * 512) + d4;
    #pragma unroll
    for (int i = 0; i < 8; ++i)
        dst[(size_t)i * 512] = o;
}

extern "C" void kernel_launch(void* const* d_in, const int* in_sizes, int n_in,
                              void* d_out, int out_size) {
    // Inputs: hidden_states, condition, Wq, bq, Wk, bk, Wv, bv, Wo, bo
    const float* cond = (const float*)d_in[1];
    const float* Wv   = (const float*)d_in[6];
    const float* bv   = (const float*)d_in[7];
    const float* Wo   = (const float*)d_in[8];
    const float* bo   = (const float*)d_in[9];
    float* out = (float*)d_out;

    static bool attr_done = false;
    if (!attr_done) {
        cudaFuncSetAttribute(gemv_tma<0>, cudaFuncAttributeMaxDynamicSharedMemorySize, SM_TOTAL);
        cudaFuncSetAttribute(gemv_tma<1>, cudaFuncAttributeMaxDynamicSharedMemorySize, SM_TOTAL);
        attr_done = true;
    }

    gemv_tma<0><<<NBLK, 256, SM_TOTAL>>>(Wv, cond, nullptr);
    gemv_tma<1><<<NBLK, 256, SM_TOTAL>>>(Wo, nullptr, bv);
    bcast_kernel<<<(BB * SS * (DD / 4) / 8) / 256, 256>>>((float4*)out, bo);
}

// round 13
// speedup vs baseline: 1.4318x; 1.4318x over previous
#include <cuda_runtime.h>
#include <cuda_bf16.h>

#define BB 4
#define SS 1024
#define DD 2048
#define RPB 8                  // rows per block
#define NBLK (DD / RPB)        // 256 blocks

// Scratch (allocation-free rule: __device__ globals; device-side refs only)
__device__ float g_v[BB * DD];
__device__ float g_o[BB * DD];

__device__ __forceinline__ float4 f4add(float4 a, float4 b) {
    return make_float4(a.x + b.x, a.y + b.y, a.z + b.z, a.w + b.w);
}

// y[b][r0+r] = sum_k x[b][k] * W[r0+r][k], 8 rows per block.
// Warp w owns k-slice [w*256,(w+1)*256); lane l owns 8 floats of it
// (two fully-coalesced float4 at +l*4 and +128+l*4), held in REGISTERS for
// all 4 batches. W streams via direct LDG.128 (no smem round-trip).
// STAGE 0: x = cond, y = g_v.  STAGE 1: x = g_v + bv, y = g_o.
template<int STAGE>
__global__ __launch_bounds__(256, 2) void gemv_reg(const float* __restrict__ W,
                                                   const float* __restrict__ cond,
                                                   const float* __restrict__ bv) {
    __shared__ float pr[8][32];    // per-warp reduced outputs

    const int tid  = threadIdx.x;
    const int wid  = tid >> 5;
    const int lane = tid & 31;
    const int r0   = blockIdx.x * RPB;
    const int ka   = wid * 256 + lane * 4;   // first float4 offset
    const int kb   = ka + 128;               // second float4 offset

    // x into registers: 4 batches x 8 floats (2 float4 each).
    float4 xa[BB], xb[BB];
    #pragma unroll
    for (int b = 0; b < BB; ++b) {
        if (STAGE == 0) {
            xa[b] = *(const float4*)(cond + b * DD + ka);
            xb[b] = *(const float4*)(cond + b * DD + kb);
        } else {
            const float4 va = *(const float4*)(g_v + b * DD + ka);
            const float4 vb = *(const float4*)(g_v + b * DD + kb);
            const float4 ba = *(const float4*)(bv + ka);
            const float4 bb = *(const float4*)(bv + kb);
            xa[b] = f4add(va, ba);
            xb[b] = f4add(vb, bb);
        }
    }

    // acc[r*4+b]: 8 rows x 4 batches of per-lane partial dots.
    float acc[32];
    #pragma unroll
    for (int i = 0; i < 32; ++i) acc[i] = 0.f;

    // Stream W rows in two half-batches of 4 (8 in-flight LDG.128 each).
    #pragma unroll
    for (int h = 0; h < 2; ++h) {
        float4 wa[4], wb[4];
        #pragma unroll
        for (int r = 0; r < 4; ++r) {
            const float* Wr = W + (size_t)(r0 + h * 4 + r) * DD;
            wa[r] = *(const float4*)(Wr + ka);
            wb[r] = *(const float4*)(Wr + kb);
        }
        #pragma unroll
        for (int r = 0; r < 4; ++r) {
            const int ri = (h * 4 + r) * 4;
            #pragma unroll
            for (int b = 0; b < BB; ++b) {
                acc[ri + b] += wa[r].x * xa[b].x + wa[r].y * xa[b].y +
                               wa[r].z * xa[b].z + wa[r].w * xa[b].w +
                               wb[r].x * xb[b].x + wb[r].y * xb[b].y +
                               wb[r].z * xb[b].z + wb[r].w * xb[b].w;
            }
        }
    }

    // Butterfly: 32 values/lane -> lane l holds full warp-sum for output
    // (row r0 + (l>>2), batch l&3). Verified mapping from R7.
    int L = 32;
    #pragma unroll
    for (int m = 16; m >= 1; m >>= 1) {
        L >>= 1;
        const bool up = (lane & m) != 0;
        #pragma unroll
        for (int j = 0; j < L; ++j) {
            const float send = up ? acc[j] : acc[j + L];
            const float recv = __shfl_xor_sync(0xffffffffu, send, m);
            acc[j] = (up ? acc[j + L] : acc[j]) + recv;
        }
    }

    pr[wid][lane] = acc[0];
    __syncthreads();

    // Cross-warp combine: 32 outputs, 8 partials each.
    if (tid < 32) {
        float s = pr[0][tid];
        #pragma unroll
        for (int w = 1; w < 8; ++w) s += pr[w][tid];
        float* y = (STAGE == 0) ? g_v : g_o;
        const int row = r0 + (tid >> 2);
        const int b   = tid & 3;
        y[b * DD + row] = s;
    }
}

// out[b][s][:] = g_o[b][:] + bo, broadcast over s; 8 stores per owner thread.
__global__ __launch_bounds__(256) void bcast_kernel(float4* __restrict__ out,
                                                    const float* __restrict__ bo) {
    const int t  = blockIdx.x * 256 + threadIdx.x;   // 256K threads
    const int d4 = t & 511;
    const int g  = t >> 9;
    const int b  = g >> 7;           // 0..3
    const int s8 = (g & 127) * 8;

    const float4* o4  = (const float4*)g_o;
    const float4* bo4 = (const float4*)bo;
    const float4 o = f4add(o4[b * 512 + d4], bo4[d4]);

    float4* dst = out + ((size_t)(b * SS + s8) * 512) + d4;
    #pragma unroll
    for (int i = 0; i < 8; ++i)
        dst[(size_t)i * 512] = o;
}

extern "C" void kernel_launch(void* const* d_in, const int* in_sizes, int n_in,
                              void* d_out, int out_size) {
    // Inputs: hidden_states, condition, Wq, bq, Wk, bk, Wv, bv, Wo, bo
    const float* cond = (const float*)d_in[1];
    const float* Wv   = (const float*)d_in[6];
    const float* bv   = (const float*)d_in[7];
    const float* Wo   = (const float*)d_in[8];
    const float* bo   = (const float*)d_in[9];
    float* out = (float*)d_out;

    gemv_reg<0><<<NBLK, 256>>>(Wv, cond, nullptr);
    gemv_reg<1><<<NBLK, 256>>>(Wo, nullptr, bv);
    bcast_kernel<<<(BB * SS * (DD / 4) / 8) / 256, 256>>>((float4*)out, bo);
}

// round 14
// speedup vs baseline: 1.4590x; 1.0190x over previous
#include <cuda_runtime.h>
#include <cuda_bf16.h>

#define BB 4
#define SS 1024
#define DD 2048
#define RPB 8                  // rows per block
#define NBLK (DD / RPB)        // 256 blocks

// Scratch (allocation-free rule: __device__ globals; device-side refs only)
__device__ float g_v[BB * DD];
__device__ float g_o[BB * DD];

__device__ __forceinline__ float4 f4add(float4 a, float4 b) {
    return make_float4(a.x + b.x, a.y + b.y, a.z + b.z, a.w + b.w);
}

// y[b][r0+r] = sum_k x[b][k] * W[r0+r][k], 8 rows per block.
// Warp w owns k-slice [w*256,(w+1)*256); lane l holds its 8 x-floats x 4
// batches in registers. ALL 24 LDG.128 (8 x + 16 W) are issued before any
// FMA: one long load window (12 KB in flight per warp) instead of two
// synchronized load/compute phases -> memory duty cycle ~doubles.
// STAGE 0: x = cond, y = g_v.  STAGE 1: x = g_v + bv, y = g_o.
template<int STAGE>
__global__ __launch_bounds__(256) void gemv_reg(const float* __restrict__ W,
                                                const float* __restrict__ cond,
                                                const float* __restrict__ bv) {
    __shared__ float pr[8][32];    // per-warp reduced outputs

    const int tid  = threadIdx.x;
    const int wid  = tid >> 5;
    const int lane = tid & 31;
    const int r0   = blockIdx.x * RPB;
    const int ka   = wid * 256 + lane * 4;   // first float4 offset
    const int kb   = ka + 128;               // second float4 offset

    // x into registers: 4 batches x 8 floats (2 float4 each).
    float4 xa[BB], xb[BB];
    #pragma unroll
    for (int b = 0; b < BB; ++b) {
        if (STAGE == 0) {
            xa[b] = *(const float4*)(cond + b * DD + ka);
            xb[b] = *(const float4*)(cond + b * DD + kb);
        } else {
            xa[b] = *(const float4*)(g_v + b * DD + ka);
            xb[b] = *(const float4*)(g_v + b * DD + kb);
        }
    }

    // ALL 16 W float4s front-batched (8 rows x 2 slices).
    float4 wa[8], wb[8];
    #pragma unroll
    for (int r = 0; r < 8; ++r) {
        const float* Wr = W + (size_t)(r0 + r) * DD;
        wa[r] = *(const float4*)(Wr + ka);
        wb[r] = *(const float4*)(Wr + kb);
    }

    if (STAGE == 1) {
        const float4 ba = *(const float4*)(bv + ka);
        const float4 bb = *(const float4*)(bv + kb);
        #pragma unroll
        for (int b = 0; b < BB; ++b) {
            xa[b] = f4add(xa[b], ba);
            xb[b] = f4add(xb[b], bb);
        }
    }

    // acc[r*4+b]: 8 rows x 4 batches of per-lane partial dots.
    float acc[32];
    #pragma unroll
    for (int r = 0; r < 8; ++r) {
        #pragma unroll
        for (int b = 0; b < BB; ++b) {
            acc[r * 4 + b] = wa[r].x * xa[b].x + wa[r].y * xa[b].y +
                             wa[r].z * xa[b].z + wa[r].w * xa[b].w +
                             wb[r].x * xb[b].x + wb[r].y * xb[b].y +
                             wb[r].z * xb[b].z + wb[r].w * xb[b].w;
        }
    }

    // Butterfly: 32 values/lane -> lane l holds full warp-sum for output
    // (row r0 + (l>>2), batch l&3). Verified mapping (R7/R13).
    int L = 32;
    #pragma unroll
    for (int m = 16; m >= 1; m >>= 1) {
        L >>= 1;
        const bool up = (lane & m) != 0;
        #pragma unroll
        for (int j = 0; j < L; ++j) {
            const float send = up ? acc[j] : acc[j + L];
            const float recv = __shfl_xor_sync(0xffffffffu, send, m);
            acc[j] = (up ? acc[j + L] : acc[j]) + recv;
        }
    }

    pr[wid][lane] = acc[0];
    __syncthreads();

    // Cross-warp combine: 32 outputs, 8 partials each.
    if (tid < 32) {
        float s = pr[0][tid];
        #pragma unroll
        for (int w = 1; w < 8; ++w) s += pr[w][tid];
        float* y = (STAGE == 0) ? g_v : g_o;
        const int row = r0 + (tid >> 2);
        const int b   = tid & 3;
        y[b * DD + row] = s;
    }
}

// out[b][s][:] = g_o[b][:] + bo, broadcast over s; 8 stores per owner thread.
__global__ __launch_bounds__(256) void bcast_kernel(float4* __restrict__ out,
                                                    const float* __restrict__ bo) {
    const int t  = blockIdx.x * 256 + threadIdx.x;   // 256K threads
    const int d4 = t & 511;
    const int g  = t >> 9;
    const int b  = g >> 7;           // 0..3
    const int s8 = (g & 127) * 8;

    const float4* o4  = (const float4*)g_o;
    const float4* bo4 = (const float4*)bo;
    const float4 o = f4add(o4[b * 512 + d4], bo4[d4]);

    float4* dst = out + ((size_t)(b * SS + s8) * 512) + d4;
    #pragma unroll
    for (int i = 0; i < 8; ++i)
        dst[(size_t)i * 512] = o;
}

extern "C" void kernel_launch(void* const* d_in, const int* in_sizes, int n_in,
                              void* d_out, int out_size) {
    // Inputs: hidden_states, condition, Wq, bq, Wk, bk, Wv, bv, Wo, bo
    const float* cond = (const float*)d_in[1];
    const float* Wv   = (const float*)d_in[6];
    const float* bv   = (const float*)d_in[7];
    const float* Wo   = (const float*)d_in[8];
    const float* bo   = (const float*)d_in[9];
    float* out = (float*)d_out;

    gemv_reg<0><<<NBLK, 256>>>(Wv, cond, nullptr);
    gemv_reg<1><<<NBLK, 256>>>(Wo, nullptr, bv);
    bcast_kernel<<<(BB * SS * (DD / 4) / 8) / 256, 256>>>((float4*)out, bo);
}